// round 6
// baseline (speedup 1.0000x reference)
#include <cuda_runtime.h>

#define N_USERS 100000
#define N_ITEMS 150000
#define NROWS   250000
#define NNZ     4000000
#define EMB     64
#define BATCH   512

#define SCAN_BLOCK 1024
#define SCAN_NBLK  ((NROWS + SCAN_BLOCK - 1) / SCAN_BLOCK)   // 245

// -------- device scratch (no allocations allowed) --------
__device__ int   g_cnt[NROWS];
__device__ int   g_rowptr[NROWS + 1];
__device__ int   g_rowpos[NROWS];
__device__ int   g_col[NNZ];
__device__ int   g_bsum[SCAN_NBLK];
__device__ float g_zA[(size_t)NROWS * EMB];    // 64 MB
__device__ float g_zB[(size_t)NROWS * EMB];    // 64 MB
__device__ float g_acc[(size_t)NROWS * EMB];   // 64 MB
__device__ float g_ubuf[BATCH * EMB];

// ============================ CSR build ============================

__global__ void k_zero_cnt() {
    int i = blockIdx.x * blockDim.x + threadIdx.x;
    if (i < NROWS) g_cnt[i] = 0;
}

__global__ void k_hist(const int* __restrict__ row) {
    int i = blockIdx.x * blockDim.x + threadIdx.x;
    if (i < NNZ) atomicAdd(&g_cnt[row[i]], 1);
}

__global__ void k_scanA() {
    __shared__ int sdata[SCAN_BLOCK];
    int i = blockIdx.x * SCAN_BLOCK + threadIdx.x;
    sdata[threadIdx.x] = (i < NROWS) ? g_cnt[i] : 0;
    __syncthreads();
    for (int s = SCAN_BLOCK / 2; s > 0; s >>= 1) {
        if (threadIdx.x < s) sdata[threadIdx.x] += sdata[threadIdx.x + s];
        __syncthreads();
    }
    if (threadIdx.x == 0) g_bsum[blockIdx.x] = sdata[0];
}

__global__ void k_scanB() {
    if (threadIdx.x == 0 && blockIdx.x == 0) {
        int acc = 0;
        for (int i = 0; i < SCAN_NBLK; i++) {
            int v = g_bsum[i];
            g_bsum[i] = acc;
            acc += v;
        }
    }
}

__global__ void k_scanC() {
    __shared__ int s[SCAN_BLOCK];
    int i = blockIdx.x * SCAN_BLOCK + threadIdx.x;
    int v = (i < NROWS) ? g_cnt[i] : 0;
    s[threadIdx.x] = v;
    __syncthreads();
    #pragma unroll
    for (int off = 1; off < SCAN_BLOCK; off <<= 1) {
        int t = (threadIdx.x >= off) ? s[threadIdx.x - off] : 0;
        __syncthreads();
        s[threadIdx.x] += t;
        __syncthreads();
    }
    int excl = s[threadIdx.x] - v + g_bsum[blockIdx.x];
    if (i < NROWS) { g_rowptr[i] = excl; g_rowpos[i] = excl; }
    if (i == NROWS) g_rowptr[NROWS] = excl;
}

__global__ void k_scatter(const int* __restrict__ row, const int* __restrict__ col) {
    int i = blockIdx.x * blockDim.x + threadIdx.x;
    if (i < NNZ) {
        int r = row[i];
        int p = atomicAdd(&g_rowpos[r], 1);
        g_col[p] = col[i];
    }
}

// ============================ SpMM kernels ============================
// warp per row; each lane owns 2 of the 64 embedding dims (float2).

__global__ void k_spmm_feat(const float* __restrict__ emb, const float* __restrict__ w) {
    int gw   = (blockIdx.x * blockDim.x + threadIdx.x) >> 5;
    int lane = threadIdx.x & 31;
    if (gw >= NROWS) return;
    int r = gw;
    int start = g_rowptr[r], end = g_rowptr[r + 1];
    int cnt = end - start;

    const float2* emb2 = (const float2*)emb;
    int sel = (r < N_USERS) ? NROWS : (NROWS + 1);
    float2 a0 = __ldg(&emb2[sel * 32 + lane]);
    float ax = a0.x, ay = a0.y;

    int e = start;
    for (; e + 4 <= end; e += 4) {
        int c0 = __ldg(&g_col[e]);
        int c1 = __ldg(&g_col[e + 1]);
        int c2 = __ldg(&g_col[e + 2]);
        int c3 = __ldg(&g_col[e + 3]);
        float2 v0 = __ldg(&emb2[c0 * 32 + lane]);
        float2 v1 = __ldg(&emb2[c1 * 32 + lane]);
        float2 v2 = __ldg(&emb2[c2 * 32 + lane]);
        float2 v3 = __ldg(&emb2[c3 * 32 + lane]);
        ax += (v0.x + v1.x) + (v2.x + v3.x);
        ay += (v0.y + v1.y) + (v2.y + v3.y);
    }
    for (; e < end; e++) {
        int c = __ldg(&g_col[e]);
        float2 v = __ldg(&emb2[c * 32 + lane]);
        ax += v.x; ay += v.y;
    }

    // z0 = d_inv * fval * w * sum ;  fval = (cnt+1)^-1/2, d_inv = max(cnt,1)^-1/2
    float scale = rsqrtf((float)(cnt + 1)) * rsqrtf((float)(cnt > 0 ? cnt : 1));
    float2 wv = __ldg(((const float2*)w) + lane);
    float2 z;
    z.x = ax * wv.x * scale;
    z.y = ay * wv.y * scale;

    size_t off = (size_t)r * 32 + lane;   // in float2 units
    ((float2*)g_zA)[off]  = z;
    __stcs(((float2*)g_acc) + off, z);
}

__global__ void k_spmm_adj(int dir) {
    int gw   = (blockIdx.x * blockDim.x + threadIdx.x) >> 5;
    int lane = threadIdx.x & 31;
    if (gw >= NROWS) return;
    int r = gw;
    const float2* zin  = (const float2*)(dir ? g_zB : g_zA);
    float2*       zout = (float2*)      (dir ? g_zA : g_zB);

    int start = g_rowptr[r], end = g_rowptr[r + 1];
    int cnt = end - start;

    float ax = 0.f, ay = 0.f;
    int e = start;
    for (; e + 4 <= end; e += 4) {
        int c0 = __ldg(&g_col[e]);
        int c1 = __ldg(&g_col[e + 1]);
        int c2 = __ldg(&g_col[e + 2]);
        int c3 = __ldg(&g_col[e + 3]);
        float2 v0 = __ldg(&zin[c0 * 32 + lane]);
        float2 v1 = __ldg(&zin[c1 * 32 + lane]);
        float2 v2 = __ldg(&zin[c2 * 32 + lane]);
        float2 v3 = __ldg(&zin[c3 * 32 + lane]);
        ax += (v0.x + v1.x) + (v2.x + v3.x);
        ay += (v0.y + v1.y) + (v2.y + v3.y);
    }
    for (; e < end; e++) {
        int c = __ldg(&g_col[e]);
        float2 v = __ldg(&zin[c * 32 + lane]);
        ax += v.x; ay += v.y;
    }

    float s2 = 1.f / (float)(cnt > 0 ? cnt : 1);   // d_inv^2
    float2 z; z.x = ax * s2; z.y = ay * s2;

    size_t off = (size_t)r * 32 + lane;
    zout[off] = z;
    float2 a = __ldcs(((const float2*)g_acc) + off);
    a.x += z.x; a.y += z.y;
    __stcs(((float2*)g_acc) + off, a);
}

// ============================ final GEMM ============================

__global__ void k_users(const int* __restrict__ users) {
    int b = blockIdx.x;
    int d = threadIdx.x;
    int u = __ldg(&users[b]);
    int cnt = g_rowptr[u + 1] - g_rowptr[u];
    float sc = 0.25f * sqrtf((float)(cnt > 0 ? cnt : 1));   // 1/(4*d_inv)
    g_ubuf[b * EMB + d] = g_acc[(size_t)u * EMB + d] * sc;
}

__device__ __forceinline__ unsigned long long dup2(float x) {
    unsigned long long r;
    asm("mov.b64 %0, {%1, %1};" : "=l"(r) : "f"(x));
    return r;
}
__device__ __forceinline__ void ffma2(unsigned long long& d,
                                      unsigned long long a,
                                      unsigned long long b) {
    asm("fma.rn.f32x2 %0, %1, %2, %0;" : "+l"(d) : "l"(a), "l"(b));
}
__device__ __forceinline__ float2 unpk(unsigned long long v) {
    float2 r;
    asm("mov.b64 {%0, %1}, %2;" : "=f"(r.x), "=f"(r.y) : "l"(v));
    return r;
}

#define GU 64
#define GJ 128

__global__ __launch_bounds__(256) void k_gemm(float* __restrict__ out) {
    __shared__ __align__(16) float sU[EMB][GU];   // [k][u]
    __shared__ __align__(16) float sI[EMB][GJ];   // [k][j]

    int tid  = threadIdx.x;
    int ublk = blockIdx.y * GU;
    int jblk = blockIdx.x * GJ;

    // ---- load user tile (already scaled in k_users), transpose to [k][u]
    {
        int u  = tid & 63;
        int kq = tid >> 6;    // 0..3
        #pragma unroll
        for (int kk = 0; kk < 4; kk++) {
            int k0 = kk * 16 + kq * 4;
            float4 v = *(const float4*)(g_ubuf + (ublk + u) * EMB + k0);
            sU[k0 + 0][u] = v.x; sU[k0 + 1][u] = v.y;
            sU[k0 + 2][u] = v.z; sU[k0 + 3][u] = v.w;
        }
    }
    // ---- load item tile, scale by 0.25*sqrt(deg), transpose to [k][j]
    {
        int j    = tid >> 1;     // 0..127
        int half = tid & 1;      // k half (0..31 / 32..63)
        int gj   = jblk + j;
        float sc = 0.f;
        const float* src = g_acc;   // dummy
        bool ok = (gj < N_ITEMS);
        if (ok) {
            int r = N_USERS + gj;
            int cnt = g_rowptr[r + 1] - g_rowptr[r];
            sc = 0.25f * sqrtf((float)(cnt > 0 ? cnt : 1));
            src = g_acc + (size_t)r * EMB + half * 32;
        }
        #pragma unroll
        for (int it = 0; it < 8; it++) {
            int k0 = half * 32 + it * 4;
            float4 v = ok ? *(const float4*)(src + it * 4) : make_float4(0.f, 0.f, 0.f, 0.f);
            sI[k0 + 0][j] = v.x * sc; sI[k0 + 1][j] = v.y * sc;
            sI[k0 + 2][j] = v.z * sc; sI[k0 + 3][j] = v.w * sc;
        }
    }
    __syncthreads();

    int tx = tid & 15;    // item group: 8 items
    int ty = tid >> 4;    // user group: 4 users

    unsigned long long acc[4][4];
    #pragma unroll
    for (int u = 0; u < 4; u++)
        #pragma unroll
        for (int p = 0; p < 4; p++) acc[u][p] = 0ull;

    #pragma unroll 8
    for (int k = 0; k < EMB; k++) {
        float4 uv = *(const float4*)&sU[k][ty * 4];
        unsigned long long a0 = dup2(uv.x), a1 = dup2(uv.y);
        unsigned long long a2 = dup2(uv.z), a3 = dup2(uv.w);
        const unsigned long long* ip = (const unsigned long long*)&sI[k][tx * 8];
        unsigned long long b0 = ip[0], b1 = ip[1], b2 = ip[2], b3 = ip[3];
        ffma2(acc[0][0], a0, b0); ffma2(acc[0][1], a0, b1);
        ffma2(acc[0][2], a0, b2); ffma2(acc[0][3], a0, b3);
        ffma2(acc[1][0], a1, b0); ffma2(acc[1][1], a1, b1);
        ffma2(acc[1][2], a1, b2); ffma2(acc[1][3], a1, b3);
        ffma2(acc[2][0], a2, b0); ffma2(acc[2][1], a2, b1);
        ffma2(acc[2][2], a2, b2); ffma2(acc[2][3], a2, b3);
        ffma2(acc[3][0], a3, b0); ffma2(acc[3][1], a3, b1);
        ffma2(acc[3][2], a3, b2); ffma2(acc[3][3], a3, b3);
    }

    int j0 = jblk + tx * 8;
    #pragma unroll
    for (int u = 0; u < 4; u++) {
        int gu = ublk + ty * 4 + u;
        float f[8];
        #pragma unroll
        for (int p = 0; p < 4; p++) {
            float2 t = unpk(acc[u][p]);
            f[2 * p] = t.x; f[2 * p + 1] = t.y;
        }
        float* op = out + (size_t)gu * N_ITEMS + j0;
        if (j0 + 8 <= N_ITEMS) {
            *(float4*)op       = make_float4(f[0], f[1], f[2], f[3]);
            *(float4*)(op + 4) = make_float4(f[4], f[5], f[6], f[7]);
        } else {
            #pragma unroll
            for (int p = 0; p < 8; p++)
                if (j0 + p < N_ITEMS) op[p] = f[p];
        }
    }
}

// ============================ launch ============================

extern "C" void kernel_launch(void* const* d_in, const int* in_sizes, int n_in,
                              void* d_out, int out_size) {
    const int*   users   = (const int*)d_in[0];
    const float* emb     = (const float*)d_in[1];
    const float* w       = (const float*)d_in[2];
    const int*   adj_row = (const int*)d_in[3];
    const int*   adj_col = (const int*)d_in[4];
    float*       out     = (float*)d_out;

    // CSR build (every launch; deterministic pattern)
    k_zero_cnt<<<(NROWS + 255) / 256, 256>>>();
    k_hist<<<(NNZ + 255) / 256, 256>>>(adj_row);
    k_scanA<<<SCAN_NBLK, SCAN_BLOCK>>>();
    k_scanB<<<1, 32>>>();
    k_scanC<<<SCAN_NBLK, SCAN_BLOCK>>>();
    k_scatter<<<(NNZ + 255) / 256, 256>>>(adj_row, adj_col);

    int spmm_blocks = (NROWS + 7) / 8;   // 8 warps/block, warp per row
    k_spmm_feat<<<spmm_blocks, 256>>>(emb, w);
    k_spmm_adj<<<spmm_blocks, 256>>>(0);  // zA -> zB
    k_spmm_adj<<<spmm_blocks, 256>>>(1);  // zB -> zA
    k_spmm_adj<<<spmm_blocks, 256>>>(0);  // zA -> zB

    k_users<<<BATCH, EMB>>>(users);
    dim3 gg((N_ITEMS + GJ - 1) / GJ, BATCH / GU);
    k_gemm<<<gg, 256>>>(out);
}

// round 15
// speedup vs baseline: 1.4987x; 1.4987x over previous
#include <cuda_runtime.h>
#include <cuda_bf16.h>
#include <cstdint>

#define N_USERS 100000
#define N_ITEMS 150000
#define NROWS   250000
#define NNZ     4000000
#define EMB     64
#define BATCH   512
#define N_ITEMS_PAD 150016   // 1172 * 128

#define SCAN_BLOCK 1024
#define SCAN_NBLK  ((NROWS + SCAN_BLOCK - 1) / SCAN_BLOCK)   // 245

// -------- device scratch (no allocations allowed) --------
__device__ int   g_cnt[NROWS];
__device__ int   g_rowptr[NROWS + 1];
__device__ int   g_rowpos[NROWS];
__device__ int   g_col[NNZ];
__device__ int   g_bsum[SCAN_NBLK];
__device__ float g_z[4][(size_t)NROWS * EMB];       // 4 x 64 MB: z0..z3
// packed bf16 tiles (2 bf16 per u32, 32 u32 per 64-dim row)
__device__ uint32_t g_ibufH[(size_t)N_ITEMS_PAD * 32];
__device__ uint32_t g_ibufL[(size_t)N_ITEMS_PAD * 32];
__device__ uint32_t g_ubufH[BATCH * 32];
__device__ uint32_t g_ubufL[BATCH * 32];

// ============================ CSR build ============================

__global__ void k_zero_cnt() {
    int i = blockIdx.x * blockDim.x + threadIdx.x;
    if (i < NROWS) g_cnt[i] = 0;
}

__global__ void k_hist(const int* __restrict__ row) {
    int i = blockIdx.x * blockDim.x + threadIdx.x;
    if (i < NNZ) atomicAdd(&g_cnt[row[i]], 1);
}

__global__ void k_scanA() {
    __shared__ int sdata[SCAN_BLOCK];
    int i = blockIdx.x * SCAN_BLOCK + threadIdx.x;
    sdata[threadIdx.x] = (i < NROWS) ? g_cnt[i] : 0;
    __syncthreads();
    for (int s = SCAN_BLOCK / 2; s > 0; s >>= 1) {
        if (threadIdx.x < s) sdata[threadIdx.x] += sdata[threadIdx.x + s];
        __syncthreads();
    }
    if (threadIdx.x == 0) g_bsum[blockIdx.x] = sdata[0];
}

__global__ void k_scanB() {
    __shared__ int s[256];
    int t = threadIdx.x;
    int v = (t < SCAN_NBLK) ? g_bsum[t] : 0;
    s[t] = v;
    __syncthreads();
    #pragma unroll
    for (int off = 1; off < 256; off <<= 1) {
        int x = (t >= off) ? s[t - off] : 0;
        __syncthreads();
        s[t] += x;
        __syncthreads();
    }
    if (t < SCAN_NBLK) g_bsum[t] = s[t] - v;   // exclusive
}

__global__ void k_scanC() {
    __shared__ int s[SCAN_BLOCK];
    int i = blockIdx.x * SCAN_BLOCK + threadIdx.x;
    int v = (i < NROWS) ? g_cnt[i] : 0;
    s[threadIdx.x] = v;
    __syncthreads();
    #pragma unroll
    for (int off = 1; off < SCAN_BLOCK; off <<= 1) {
        int t = (threadIdx.x >= off) ? s[threadIdx.x - off] : 0;
        __syncthreads();
        s[threadIdx.x] += t;
        __syncthreads();
    }
    int excl = s[threadIdx.x] - v + g_bsum[blockIdx.x];
    if (i < NROWS) { g_rowptr[i] = excl; g_rowpos[i] = excl; }
    if (i == NROWS) g_rowptr[NROWS] = excl;
}

__global__ void k_scatter(const int* __restrict__ row, const int* __restrict__ col) {
    int i = blockIdx.x * blockDim.x + threadIdx.x;
    if (i < NNZ) {
        int r = row[i];
        int p = atomicAdd(&g_rowpos[r], 1);
        g_col[p] = col[i];
    }
}

// ============================ SpMM kernels ============================
// warp per row; each lane owns 2 of the 64 embedding dims (float2).

__global__ void k_spmm_feat(const float* __restrict__ emb, const float* __restrict__ w) {
    int gw   = (blockIdx.x * blockDim.x + threadIdx.x) >> 5;
    int lane = threadIdx.x & 31;
    if (gw >= NROWS) return;
    int r = gw;
    int start = g_rowptr[r], end = g_rowptr[r + 1];
    int cnt = end - start;

    const float2* emb2 = (const float2*)emb;
    int sel = (r < N_USERS) ? NROWS : (NROWS + 1);
    float2 a0 = __ldg(&emb2[sel * 32 + lane]);
    float ax = a0.x, ay = a0.y;

    int e = start;
    for (; e + 4 <= end; e += 4) {
        int c0 = __ldg(&g_col[e]);
        int c1 = __ldg(&g_col[e + 1]);
        int c2 = __ldg(&g_col[e + 2]);
        int c3 = __ldg(&g_col[e + 3]);
        float2 v0 = __ldg(&emb2[c0 * 32 + lane]);
        float2 v1 = __ldg(&emb2[c1 * 32 + lane]);
        float2 v2 = __ldg(&emb2[c2 * 32 + lane]);
        float2 v3 = __ldg(&emb2[c3 * 32 + lane]);
        ax += (v0.x + v1.x) + (v2.x + v3.x);
        ay += (v0.y + v1.y) + (v2.y + v3.y);
    }
    for (; e < end; e++) {
        int c = __ldg(&g_col[e]);
        float2 v = __ldg(&emb2[c * 32 + lane]);
        ax += v.x; ay += v.y;
    }

    float scale = rsqrtf((float)(cnt + 1)) * rsqrtf((float)(cnt > 0 ? cnt : 1));
    float2 wv = __ldg(((const float2*)w) + lane);
    float2 z;
    z.x = ax * wv.x * scale;
    z.y = ay * wv.y * scale;

    ((float2*)g_z[0])[(size_t)r * 32 + lane] = z;
}

__global__ void k_spmm_adj(int layer) {
    int gw   = (blockIdx.x * blockDim.x + threadIdx.x) >> 5;
    int lane = threadIdx.x & 31;
    if (gw >= NROWS) return;
    int r = gw;
    const float2* zin  = (const float2*)g_z[layer - 1];
    float2*       zout = (float2*)g_z[layer];

    int start = g_rowptr[r], end = g_rowptr[r + 1];
    int cnt = end - start;

    float ax = 0.f, ay = 0.f;
    int e = start;
    for (; e + 4 <= end; e += 4) {
        int c0 = __ldg(&g_col[e]);
        int c1 = __ldg(&g_col[e + 1]);
        int c2 = __ldg(&g_col[e + 2]);
        int c3 = __ldg(&g_col[e + 3]);
        float2 v0 = __ldg(&zin[c0 * 32 + lane]);
        float2 v1 = __ldg(&zin[c1 * 32 + lane]);
        float2 v2 = __ldg(&zin[c2 * 32 + lane]);
        float2 v3 = __ldg(&zin[c3 * 32 + lane]);
        ax += (v0.x + v1.x) + (v2.x + v3.x);
        ay += (v0.y + v1.y) + (v2.y + v3.y);
    }
    for (; e < end; e++) {
        int c = __ldg(&g_col[e]);
        float2 v = __ldg(&zin[c * 32 + lane]);
        ax += v.x; ay += v.y;
    }

    float s2 = 1.f / (float)(cnt > 0 ? cnt : 1);   // d_inv^2
    float2 z; z.x = ax * s2; z.y = ay * s2;
    zout[(size_t)r * 32 + lane] = z;
}

// ============================ bf16 hi/lo prep ============================

__device__ __forceinline__ void split2(float x, float y, uint32_t& hi, uint32_t& lo) {
    __nv_bfloat16 hx = __float2bfloat16(x), hy = __float2bfloat16(y);
    hi = (uint32_t)__bfloat16_as_ushort(hx) | ((uint32_t)__bfloat16_as_ushort(hy) << 16);
    __nv_bfloat16 lx = __float2bfloat16(x - __bfloat162float(hx));
    __nv_bfloat16 ly = __float2bfloat16(y - __bfloat162float(hy));
    lo = (uint32_t)__bfloat16_as_ushort(lx) | ((uint32_t)__bfloat16_as_ushort(ly) << 16);
}

// one thread per (row, 4 cols): i in [0, N_ITEMS_PAD*16)
__global__ void k_prep_items() {
    int i = blockIdx.x * blockDim.x + threadIdx.x;
    if (i >= N_ITEMS_PAD * 16) return;
    int r = i >> 4, kk = i & 15;
    float4 v = make_float4(0.f, 0.f, 0.f, 0.f);
    if (r < N_ITEMS) {
        int row = N_USERS + r;
        int cnt = g_rowptr[row + 1] - g_rowptr[row];
        float sc = 0.25f * sqrtf((float)(cnt > 0 ? cnt : 1));
        size_t o = (size_t)row * EMB + kk * 4;
        float4 a = *(const float4*)&g_z[0][o];
        float4 b = *(const float4*)&g_z[1][o];
        float4 c = *(const float4*)&g_z[2][o];
        float4 d = *(const float4*)&g_z[3][o];
        v.x = (a.x + b.x + c.x + d.x) * sc;
        v.y = (a.y + b.y + c.y + d.y) * sc;
        v.z = (a.z + b.z + c.z + d.z) * sc;
        v.w = (a.w + b.w + c.w + d.w) * sc;
    }
    uint32_t h0, l0, h1, l1;
    split2(v.x, v.y, h0, l0);
    split2(v.z, v.w, h1, l1);
    ((uint2*)g_ibufH)[i] = make_uint2(h0, h1);
    ((uint2*)g_ibufL)[i] = make_uint2(l0, l1);
}

__global__ void k_users(const int* __restrict__ users) {
    int i = blockIdx.x * blockDim.x + threadIdx.x;
    if (i >= BATCH * 16) return;
    int b = i >> 4, kk = i & 15;
    int u = __ldg(&users[b]);
    int cnt = g_rowptr[u + 1] - g_rowptr[u];
    float sc = 0.25f * sqrtf((float)(cnt > 0 ? cnt : 1));
    size_t o = (size_t)u * EMB + kk * 4;
    float4 a = *(const float4*)&g_z[0][o];
    float4 bb = *(const float4*)&g_z[1][o];
    float4 c = *(const float4*)&g_z[2][o];
    float4 d = *(const float4*)&g_z[3][o];
    float4 v;
    v.x = (a.x + bb.x + c.x + d.x) * sc;
    v.y = (a.y + bb.y + c.y + d.y) * sc;
    v.z = (a.z + bb.z + c.z + d.z) * sc;
    v.w = (a.w + bb.w + c.w + d.w) * sc;
    uint32_t h0, l0, h1, l1;
    split2(v.x, v.y, h0, l0);
    split2(v.z, v.w, h1, l1);
    ((uint2*)g_ubufH)[i] = make_uint2(h0, h1);
    ((uint2*)g_ubufL)[i] = make_uint2(l0, l1);
}

// ============================ HMMA bf16 GEMM ============================
// out[512, 150000] = U @ I^T, hi/lo split: Ah*Bh + Ah*Bl + Al*Bh.
// CTA = 128 users x 128 items; 8 warps (2x4), warp tile 64x32.

#define SWZ(o) ((o) ^ (((o) >> 3) & 0x70))

__device__ __forceinline__ uint32_t smem_u32(const void* p) {
    uint32_t a;
    asm("{ .reg .u64 t; cvta.to.shared.u64 t, %1; cvt.u32.u64 %0, t; }"
        : "=r"(a) : "l"(p));
    return a;
}

#define LDSM4(r0, r1, r2, r3, addr) \
    asm volatile("ldmatrix.sync.aligned.m8n8.x4.shared.b16 {%0,%1,%2,%3}, [%4];" \
        : "=r"(r0), "=r"(r1), "=r"(r2), "=r"(r3) : "r"(addr))

#define MMA16816(c, a, b0, b1) \
    asm volatile("mma.sync.aligned.m16n8k16.row.col.f32.bf16.bf16.f32 " \
        "{%0,%1,%2,%3}, {%4,%5,%6,%7}, {%8,%9}, {%0,%1,%2,%3};" \
        : "+f"((c)[0]), "+f"((c)[1]), "+f"((c)[2]), "+f"((c)[3]) \
        : "r"((a)[0]), "r"((a)[1]), "r"((a)[2]), "r"((a)[3]), "r"(b0), "r"(b1))

#define GEMM_SMEM 65536   // 4 tiles x 16KB (Ah, Al, Bh, Bl)

__global__ __launch_bounds__(256) void k_gemm(float* __restrict__ out) {
    extern __shared__ char sm[];
    char* sAh = sm;
    char* sAl = sm + 16384;
    char* sBh = sm + 32768;
    char* sBl = sm + 49152;

    int t    = threadIdx.x;
    int wid  = t >> 5, lane = t & 31;
    int mt   = blockIdx.x;     // user tile 0..3   (fast -> item tile L2 reuse)
    int jblk = blockIdx.y;     // item tile 0..1171

    // ---- load tiles: 128 rows x 128 B each, SW128-swizzled, fully coalesced
    {
        const uint4* aH = (const uint4*)(g_ubufH + (size_t)mt * 128 * 32);
        const uint4* aL = (const uint4*)(g_ubufL + (size_t)mt * 128 * 32);
        const uint4* bH = (const uint4*)(g_ibufH + (size_t)jblk * 128 * 32);
        const uint4* bL = (const uint4*)(g_ibufL + (size_t)jblk * 128 * 32);
        #pragma unroll
        for (int q = 0; q < 4; q++) {
            int idx = q * 256 + t;                 // 1024 uint4 per tile
            uint32_t off = SWZ((uint32_t)(idx * 16));
            *(uint4*)(sAh + off) = aH[idx];
            *(uint4*)(sAl + off) = aL[idx];
            *(uint4*)(sBh + off) = bH[idx];
            *(uint4*)(sBl + off) = bL[idx];
        }
    }
    __syncthreads();

    int wm = wid >> 2;            // 0..1 -> m_base 0/64
    int wn = wid & 3;             // 0..3 -> n_base 0/32/64/96
    int m_base = wm * 64;
    int n_base = wn * 32;

    // per-lane ldmatrix source coords (byte offsets within a tile)
    int a_row = m_base + (lane & 15);
    int a_kc  = (lane >> 4) * 16;                       // +8 cols
    int b_row = n_base + (lane & 7) + ((lane >> 4) << 3);
    int b_kc  = ((lane >> 3) & 1) * 16;

    float acc[4][4][4];
    #pragma unroll
    for (int i = 0; i < 4; i++)
        #pragma unroll
        for (int j = 0; j < 4; j++)
            #pragma unroll
            for (int q = 0; q < 4; q++) acc[i][j][q] = 0.f;

    const char* Ap[3] = { sAh, sAh, sAl };
    const char* Bp[3] = { sBh, sBl, sBh };

    #pragma unroll
    for (int p = 0; p < 3; p++) {
        #pragma unroll
        for (int ks = 0; ks < 4; ks++) {        // K = 64, 16 per step = 32 B
            uint32_t a[4][4];
            #pragma unroll
            for (int mi = 0; mi < 4; mi++) {
                uint32_t off = SWZ((uint32_t)((a_row + mi * 16) * 128 + ks * 32 + a_kc));
                uint32_t ad = smem_u32(Ap[p] + off);
                LDSM4(a[mi][0], a[mi][1], a[mi][2], a[mi][3], ad);
            }
            uint32_t bb[2][4];
            #pragma unroll
            for (int nh = 0; nh < 2; nh++) {    // each x4 covers two n8 tiles
                uint32_t off = SWZ((uint32_t)((b_row + nh * 16) * 128 + ks * 32 + b_kc));
                uint32_t ad = smem_u32(Bp[p] + off);
                LDSM4(bb[nh][0], bb[nh][1], bb[nh][2], bb[nh][3], ad);
            }
            #pragma unroll
            for (int mi = 0; mi < 4; mi++)
                #pragma unroll
                for (int nj = 0; nj < 4; nj++)
                    MMA16816(acc[mi][nj], a[mi],
                             bb[nj >> 1][(nj & 1) * 2],
                             bb[nj >> 1][(nj & 1) * 2 + 1]);
        }
    }

    // ---- epilogue: c0,c1 -> (row, col..col+1); c2,c3 -> (row+8, ...)
    int gj0 = jblk * 128 + n_base;
    #pragma unroll
    for (int mi = 0; mi < 4; mi++) {
        int r0 = mt * 128 + m_base + mi * 16 + (lane >> 2);
        float* row0 = out + (size_t)r0 * N_ITEMS;
        float* row1 = row0 + (size_t)8 * N_ITEMS;
        #pragma unroll
        for (int nj = 0; nj < 4; nj++) {
            int c = gj0 + nj * 8 + (lane & 3) * 2;
            if (c < N_ITEMS) {   // N_ITEMS even, c even -> pair always in-bounds
                *(float2*)(row0 + c) = make_float2(acc[mi][nj][0], acc[mi][nj][1]);
                *(float2*)(row1 + c) = make_float2(acc[mi][nj][2], acc[mi][nj][3]);
            }
        }
    }
}

// ============================ launch ============================

extern "C" void kernel_launch(void* const* d_in, const int* in_sizes, int n_in,
                              void* d_out, int out_size) {
    const int*   users   = (const int*)d_in[0];
    const float* emb     = (const float*)d_in[1];
    const float* w       = (const float*)d_in[2];
    const int*   adj_row = (const int*)d_in[3];
    const int*   adj_col = (const int*)d_in[4];
    float*       out     = (float*)d_out;

    cudaFuncSetAttribute(k_gemm, cudaFuncAttributeMaxDynamicSharedMemorySize, GEMM_SMEM);

    // CSR build
    k_zero_cnt<<<(NROWS + 255) / 256, 256>>>();
    k_hist<<<(NNZ + 255) / 256, 256>>>(adj_row);
    k_scanA<<<SCAN_NBLK, SCAN_BLOCK>>>();
    k_scanB<<<1, 256>>>();
    k_scanC<<<SCAN_NBLK, SCAN_BLOCK>>>();
    k_scatter<<<(NNZ + 255) / 256, 256>>>(adj_row, adj_col);

    int spmm_blocks = (NROWS + 7) / 8;   // 8 warps/block, warp per row
    k_spmm_feat<<<spmm_blocks, 256>>>(emb, w);
    k_spmm_adj<<<spmm_blocks, 256>>>(1);  // z0 -> z1
    k_spmm_adj<<<spmm_blocks, 256>>>(2);  // z1 -> z2
    k_spmm_adj<<<spmm_blocks, 256>>>(3);  // z2 -> z3

    k_users<<<(BATCH * 16 + 255) / 256, 256>>>(users);
    k_prep_items<<<(N_ITEMS_PAD * 16 + 255) / 256, 256>>>();

    dim3 gg(4, (N_ITEMS + 127) / 128);   // (mt, jblk) = (4, 1172)
    k_gemm<<<gg, 256, GEMM_SMEM>>>(out);
}

// round 16
// speedup vs baseline: 1.8105x; 1.2080x over previous
#include <cuda_runtime.h>
#include <cuda_bf16.h>
#include <cstdint>

#define N_USERS 100000
#define N_ITEMS 150000
#define NROWS   250000
#define NNZ     4000000
#define EMB     64
#define BATCH   512
#define N_ITEMS_PAD 150016   // 1172 * 128

#define SCAN_BLOCK 1024
#define SCAN_NBLK  ((NROWS + SCAN_BLOCK - 1) / SCAN_BLOCK)   // 245

// -------- device scratch (no allocations allowed) --------
__device__ int   g_cnt[NROWS];
__device__ int   g_rowptr[NROWS + 1];
__device__ int   g_rowpos[NROWS];
__device__ int   g_col[NNZ];
__device__ int   g_bsum[SCAN_NBLK];
__device__ float g_z[3][(size_t)NROWS * EMB];       // z0, z1, z2 (64 MB each)
// packed bf16 tiles (2 bf16 per u32, 32 u32 per 64-dim row)
__device__ uint32_t g_ibufH[(size_t)N_ITEMS_PAD * 32];
__device__ uint32_t g_ibufL[(size_t)N_ITEMS_PAD * 32];
__device__ uint32_t g_ubufH[BATCH * 32];
__device__ uint32_t g_ubufL[BATCH * 32];

// ============================ CSR build ============================

__global__ void k_zero_cnt() {
    int i = blockIdx.x * blockDim.x + threadIdx.x;
    if (i < NROWS) g_cnt[i] = 0;
}

__global__ void k_hist(const int* __restrict__ row) {
    int i = blockIdx.x * blockDim.x + threadIdx.x;
    if (i < NNZ) atomicAdd(&g_cnt[row[i]], 1);
}

__global__ void k_scanA() {
    __shared__ int sdata[SCAN_BLOCK];
    int i = blockIdx.x * SCAN_BLOCK + threadIdx.x;
    sdata[threadIdx.x] = (i < NROWS) ? g_cnt[i] : 0;
    __syncthreads();
    for (int s = SCAN_BLOCK / 2; s > 0; s >>= 1) {
        if (threadIdx.x < s) sdata[threadIdx.x] += sdata[threadIdx.x + s];
        __syncthreads();
    }
    if (threadIdx.x == 0) g_bsum[blockIdx.x] = sdata[0];
}

__global__ void k_scanB() {
    __shared__ int s[256];
    int t = threadIdx.x;
    int v = (t < SCAN_NBLK) ? g_bsum[t] : 0;
    s[t] = v;
    __syncthreads();
    #pragma unroll
    for (int off = 1; off < 256; off <<= 1) {
        int x = (t >= off) ? s[t - off] : 0;
        __syncthreads();
        s[t] += x;
        __syncthreads();
    }
    if (t < SCAN_NBLK) g_bsum[t] = s[t] - v;   // exclusive
}

__global__ void k_scanC() {
    __shared__ int s[SCAN_BLOCK];
    int i = blockIdx.x * SCAN_BLOCK + threadIdx.x;
    int v = (i < NROWS) ? g_cnt[i] : 0;
    s[threadIdx.x] = v;
    __syncthreads();
    #pragma unroll
    for (int off = 1; off < SCAN_BLOCK; off <<= 1) {
        int t = (threadIdx.x >= off) ? s[threadIdx.x - off] : 0;
        __syncthreads();
        s[threadIdx.x] += t;
        __syncthreads();
    }
    int excl = s[threadIdx.x] - v + g_bsum[blockIdx.x];
    if (i < NROWS) { g_rowptr[i] = excl; g_rowpos[i] = excl; }
    if (i == NROWS) g_rowptr[NROWS] = excl;
}

__global__ void k_scatter(const int* __restrict__ row, const int* __restrict__ col) {
    int i = blockIdx.x * blockDim.x + threadIdx.x;
    if (i < NNZ) {
        int r = row[i];
        int p = atomicAdd(&g_rowpos[r], 1);
        g_col[p] = col[i];
    }
}

// ============================ SpMM kernels ============================
// half-warp per row: 16 lanes x float4 (16 B) cover the 64-dim row.
// 2 rows per warp, 4-edge unroll -> 8 LDG.128 gathers in flight per warp.

__global__ void k_spmm_feat(const float* __restrict__ emb, const float* __restrict__ w) {
    int idx  = blockIdx.x * blockDim.x + threadIdx.x;
    int r    = idx >> 4;
    int lane = idx & 15;
    if (r >= NROWS) return;
    int start = g_rowptr[r], end = g_rowptr[r + 1];
    int cnt = end - start;

    const float4* emb4 = (const float4*)emb;
    int sel = (r < N_USERS) ? NROWS : (NROWS + 1);
    float4 s = __ldg(&emb4[(size_t)sel * 16 + lane]);

    int e = start;
    for (; e + 4 <= end; e += 4) {
        int c0 = __ldg(&g_col[e]);
        int c1 = __ldg(&g_col[e + 1]);
        int c2 = __ldg(&g_col[e + 2]);
        int c3 = __ldg(&g_col[e + 3]);
        float4 v0 = __ldg(&emb4[(size_t)c0 * 16 + lane]);
        float4 v1 = __ldg(&emb4[(size_t)c1 * 16 + lane]);
        float4 v2 = __ldg(&emb4[(size_t)c2 * 16 + lane]);
        float4 v3 = __ldg(&emb4[(size_t)c3 * 16 + lane]);
        s.x += (v0.x + v1.x) + (v2.x + v3.x);
        s.y += (v0.y + v1.y) + (v2.y + v3.y);
        s.z += (v0.z + v1.z) + (v2.z + v3.z);
        s.w += (v0.w + v1.w) + (v2.w + v3.w);
    }
    for (; e < end; e++) {
        int c = __ldg(&g_col[e]);
        float4 v = __ldg(&emb4[(size_t)c * 16 + lane]);
        s.x += v.x; s.y += v.y; s.z += v.z; s.w += v.w;
    }

    float scale = rsqrtf((float)(cnt + 1)) * rsqrtf((float)(cnt > 0 ? cnt : 1));
    float4 wv = __ldg(((const float4*)w) + lane);
    float4 z;
    z.x = s.x * wv.x * scale;
    z.y = s.y * wv.y * scale;
    z.z = s.z * wv.z * scale;
    z.w = s.w * wv.w * scale;
    ((float4*)g_z[0])[(size_t)r * 16 + lane] = z;
}

__global__ void k_spmm_adj(int layer) {   // full passes: layer = 1, 2
    int idx  = blockIdx.x * blockDim.x + threadIdx.x;
    int r    = idx >> 4;
    int lane = idx & 15;
    if (r >= NROWS) return;
    const float4* zin  = (const float4*)g_z[layer - 1];
    float4*       zout = (float4*)g_z[layer];

    int start = g_rowptr[r], end = g_rowptr[r + 1];
    int cnt = end - start;

    float4 s = make_float4(0.f, 0.f, 0.f, 0.f);
    int e = start;
    for (; e + 4 <= end; e += 4) {
        int c0 = __ldg(&g_col[e]);
        int c1 = __ldg(&g_col[e + 1]);
        int c2 = __ldg(&g_col[e + 2]);
        int c3 = __ldg(&g_col[e + 3]);
        float4 v0 = __ldg(&zin[(size_t)c0 * 16 + lane]);
        float4 v1 = __ldg(&zin[(size_t)c1 * 16 + lane]);
        float4 v2 = __ldg(&zin[(size_t)c2 * 16 + lane]);
        float4 v3 = __ldg(&zin[(size_t)c3 * 16 + lane]);
        s.x += (v0.x + v1.x) + (v2.x + v3.x);
        s.y += (v0.y + v1.y) + (v2.y + v3.y);
        s.z += (v0.z + v1.z) + (v2.z + v3.z);
        s.w += (v0.w + v1.w) + (v2.w + v3.w);
    }
    for (; e < end; e++) {
        int c = __ldg(&g_col[e]);
        float4 v = __ldg(&zin[(size_t)c * 16 + lane]);
        s.x += v.x; s.y += v.y; s.z += v.z; s.w += v.w;
    }

    float s2 = 1.f / (float)(cnt > 0 ? cnt : 1);   // d_inv^2
    float4 z; z.x = s.x * s2; z.y = s.y * s2; z.z = s.z * s2; z.w = s.w * s2;
    zout[(size_t)r * 16 + lane] = z;
}

// ============================ bf16 hi/lo helpers ============================

__device__ __forceinline__ void split2(float x, float y, uint32_t& hi, uint32_t& lo) {
    __nv_bfloat16 hx = __float2bfloat16(x), hy = __float2bfloat16(y);
    hi = (uint32_t)__bfloat16_as_ushort(hx) | ((uint32_t)__bfloat16_as_ushort(hy) << 16);
    __nv_bfloat16 lx = __float2bfloat16(x - __bfloat162float(hx));
    __nv_bfloat16 ly = __float2bfloat16(y - __bfloat162float(hy));
    lo = (uint32_t)__bfloat16_as_ushort(lx) | ((uint32_t)__bfloat16_as_ushort(ly) << 16);
}

// pass 3, item rows only, fused with item-tile prep:
// z3 = dinv2 * sum(z2[cols]); v = (z0+z1+z2+z3)*0.25*sqrt(deg) -> bf16 hi/lo
__global__ void k_spmm_adj3_items() {
    int idx  = blockIdx.x * blockDim.x + threadIdx.x;
    int hw   = idx >> 4;          // item index
    int lane = idx & 15;
    if (hw >= N_ITEMS) return;
    int r = N_USERS + hw;
    int start = g_rowptr[r], end = g_rowptr[r + 1];
    int cnt = end - start;

    const float4* zin = (const float4*)g_z[2];
    float4 s = make_float4(0.f, 0.f, 0.f, 0.f);
    int e = start;
    for (; e + 4 <= end; e += 4) {
        int c0 = __ldg(&g_col[e]);
        int c1 = __ldg(&g_col[e + 1]);
        int c2 = __ldg(&g_col[e + 2]);
        int c3 = __ldg(&g_col[e + 3]);
        float4 v0 = __ldg(&zin[(size_t)c0 * 16 + lane]);
        float4 v1 = __ldg(&zin[(size_t)c1 * 16 + lane]);
        float4 v2 = __ldg(&zin[(size_t)c2 * 16 + lane]);
        float4 v3 = __ldg(&zin[(size_t)c3 * 16 + lane]);
        s.x += (v0.x + v1.x) + (v2.x + v3.x);
        s.y += (v0.y + v1.y) + (v2.y + v3.y);
        s.z += (v0.z + v1.z) + (v2.z + v3.z);
        s.w += (v0.w + v1.w) + (v2.w + v3.w);
    }
    for (; e < end; e++) {
        int c = __ldg(&g_col[e]);
        float4 v = __ldg(&zin[(size_t)c * 16 + lane]);
        s.x += v.x; s.y += v.y; s.z += v.z; s.w += v.w;
    }

    float s2 = 1.f / (float)(cnt > 0 ? cnt : 1);
    size_t o = (size_t)r * 16 + lane;
    float4 a = __ldg((const float4*)g_z[0] + o);
    float4 b = __ldg((const float4*)g_z[1] + o);
    float4 c = __ldg((const float4*)g_z[2] + o);
    float sc = 0.25f * sqrtf((float)(cnt > 0 ? cnt : 1));
    float4 v;
    v.x = (a.x + b.x + c.x + s.x * s2) * sc;
    v.y = (a.y + b.y + c.y + s.y * s2) * sc;
    v.z = (a.z + b.z + c.z + s.z * s2) * sc;
    v.w = (a.w + b.w + c.w + s.w * s2) * sc;

    uint32_t h0, l0, h1, l1;
    split2(v.x, v.y, h0, l0);
    split2(v.z, v.w, h1, l1);
    ((uint2*)g_ibufH)[(size_t)hw * 16 + lane] = make_uint2(h0, h1);
    ((uint2*)g_ibufL)[(size_t)hw * 16 + lane] = make_uint2(l0, l1);
}

__global__ void k_pad_items() {
    int i = blockIdx.x * blockDim.x + threadIdx.x;
    if (i < (N_ITEMS_PAD - N_ITEMS) * 32) {
        g_ibufH[(size_t)N_ITEMS * 32 + i] = 0;
        g_ibufL[(size_t)N_ITEMS * 32 + i] = 0;
    }
}

// user prep: z3[u] computed on the fly from z2 (pass 3 skipped user rows)
__global__ void k_users(const int* __restrict__ users) {
    int idx  = blockIdx.x * blockDim.x + threadIdx.x;
    int hw   = idx >> 4;          // batch index
    int lane = idx & 15;
    if (hw >= BATCH) return;
    int u = __ldg(&users[hw]);
    int start = g_rowptr[u], end = g_rowptr[u + 1];
    int cnt = end - start;

    const float4* zin = (const float4*)g_z[2];
    float4 s = make_float4(0.f, 0.f, 0.f, 0.f);
    for (int e = start; e < end; e++) {
        int c = __ldg(&g_col[e]);
        float4 v = __ldg(&zin[(size_t)c * 16 + lane]);
        s.x += v.x; s.y += v.y; s.z += v.z; s.w += v.w;
    }
    float s2 = 1.f / (float)(cnt > 0 ? cnt : 1);
    size_t o = (size_t)u * 16 + lane;
    float4 a = __ldg((const float4*)g_z[0] + o);
    float4 b = __ldg((const float4*)g_z[1] + o);
    float4 c = __ldg((const float4*)g_z[2] + o);
    float sc = 0.25f * sqrtf((float)(cnt > 0 ? cnt : 1));
    float4 v;
    v.x = (a.x + b.x + c.x + s.x * s2) * sc;
    v.y = (a.y + b.y + c.y + s.y * s2) * sc;
    v.z = (a.z + b.z + c.z + s.z * s2) * sc;
    v.w = (a.w + b.w + c.w + s.w * s2) * sc;

    uint32_t h0, l0, h1, l1;
    split2(v.x, v.y, h0, l0);
    split2(v.z, v.w, h1, l1);
    ((uint2*)g_ubufH)[(size_t)hw * 16 + lane] = make_uint2(h0, h1);
    ((uint2*)g_ubufL)[(size_t)hw * 16 + lane] = make_uint2(l0, l1);
}

// ============================ HMMA bf16 GEMM ============================
// out[512, 150000] = U @ I^T, hi/lo split: Ah*Bh + Ah*Bl + Al*Bh.
// CTA = 128 users x 128 items; 8 warps (2x4), warp tile 64x32.

#define SWZ(o) ((o) ^ (((o) >> 3) & 0x70))

__device__ __forceinline__ uint32_t smem_u32(const void* p) {
    uint32_t a;
    asm("{ .reg .u64 t; cvta.to.shared.u64 t, %1; cvt.u32.u64 %0, t; }"
        : "=r"(a) : "l"(p));
    return a;
}

#define LDSM4(r0, r1, r2, r3, addr) \
    asm volatile("ldmatrix.sync.aligned.m8n8.x4.shared.b16 {%0,%1,%2,%3}, [%4];" \
        : "=r"(r0), "=r"(r1), "=r"(r2), "=r"(r3) : "r"(addr))

#define MMA16816(c, a, b0, b1) \
    asm volatile("mma.sync.aligned.m16n8k16.row.col.f32.bf16.bf16.f32 " \
        "{%0,%1,%2,%3}, {%4,%5,%6,%7}, {%8,%9}, {%0,%1,%2,%3};" \
        : "+f"((c)[0]), "+f"((c)[1]), "+f"((c)[2]), "+f"((c)[3]) \
        : "r"((a)[0]), "r"((a)[1]), "r"((a)[2]), "r"((a)[3]), "r"(b0), "r"(b1))

#define GEMM_SMEM 65536   // 4 tiles x 16KB (Ah, Al, Bh, Bl)

__global__ __launch_bounds__(256) void k_gemm(float* __restrict__ out) {
    extern __shared__ char sm[];
    char* sAh = sm;
    char* sAl = sm + 16384;
    char* sBh = sm + 32768;
    char* sBl = sm + 49152;

    int t    = threadIdx.x;
    int wid  = t >> 5, lane = t & 31;
    int mt   = blockIdx.x;     // user tile 0..3   (fast -> item tile L2 reuse)
    int jblk = blockIdx.y;     // item tile 0..1171

    {
        const uint4* aH = (const uint4*)(g_ubufH + (size_t)mt * 128 * 32);
        const uint4* aL = (const uint4*)(g_ubufL + (size_t)mt * 128 * 32);
        const uint4* bH = (const uint4*)(g_ibufH + (size_t)jblk * 128 * 32);
        const uint4* bL = (const uint4*)(g_ibufL + (size_t)jblk * 128 * 32);
        #pragma unroll
        for (int q = 0; q < 4; q++) {
            int idx = q * 256 + t;                 // 1024 uint4 per tile
            uint32_t off = SWZ((uint32_t)(idx * 16));
            *(uint4*)(sAh + off) = aH[idx];
            *(uint4*)(sAl + off) = aL[idx];
            *(uint4*)(sBh + off) = bH[idx];
            *(uint4*)(sBl + off) = bL[idx];
        }
    }
    __syncthreads();

    int wm = wid >> 2;            // 0..1 -> m_base 0/64
    int wn = wid & 3;             // 0..3 -> n_base 0/32/64/96
    int m_base = wm * 64;
    int n_base = wn * 32;

    int a_row = m_base + (lane & 15);
    int a_kc  = (lane >> 4) * 16;
    int b_row = n_base + (lane & 7) + ((lane >> 4) << 3);
    int b_kc  = ((lane >> 3) & 1) * 16;

    float acc[4][4][4];
    #pragma unroll
    for (int i = 0; i < 4; i++)
        #pragma unroll
        for (int j = 0; j < 4; j++)
            #pragma unroll
            for (int q = 0; q < 4; q++) acc[i][j][q] = 0.f;

    const char* Ap[3] = { sAh, sAh, sAl };
    const char* Bp[3] = { sBh, sBl, sBh };

    #pragma unroll
    for (int p = 0; p < 3; p++) {
        #pragma unroll
        for (int ks = 0; ks < 4; ks++) {        // K = 64, 16 per step = 32 B
            uint32_t a[4][4];
            #pragma unroll
            for (int mi = 0; mi < 4; mi++) {
                uint32_t off = SWZ((uint32_t)((a_row + mi * 16) * 128 + ks * 32 + a_kc));
                uint32_t ad = smem_u32(Ap[p] + off);
                LDSM4(a[mi][0], a[mi][1], a[mi][2], a[mi][3], ad);
            }
            uint32_t bb[2][4];
            #pragma unroll
            for (int nh = 0; nh < 2; nh++) {
                uint32_t off = SWZ((uint32_t)((b_row + nh * 16) * 128 + ks * 32 + b_kc));
                uint32_t ad = smem_u32(Bp[p] + off);
                LDSM4(bb[nh][0], bb[nh][1], bb[nh][2], bb[nh][3], ad);
            }
            #pragma unroll
            for (int mi = 0; mi < 4; mi++)
                #pragma unroll
                for (int nj = 0; nj < 4; nj++)
                    MMA16816(acc[mi][nj], a[mi],
                             bb[nj >> 1][(nj & 1) * 2],
                             bb[nj >> 1][(nj & 1) * 2 + 1]);
        }
    }

    int gj0 = jblk * 128 + n_base;
    #pragma unroll
    for (int mi = 0; mi < 4; mi++) {
        int r0 = mt * 128 + m_base + mi * 16 + (lane >> 2);
        float* row0 = out + (size_t)r0 * N_ITEMS;
        float* row1 = row0 + (size_t)8 * N_ITEMS;
        #pragma unroll
        for (int nj = 0; nj < 4; nj++) {
            int c = gj0 + nj * 8 + (lane & 3) * 2;
            if (c < N_ITEMS) {
                *(float2*)(row0 + c) = make_float2(acc[mi][nj][0], acc[mi][nj][1]);
                *(float2*)(row1 + c) = make_float2(acc[mi][nj][2], acc[mi][nj][3]);
            }
        }
    }
}

// ============================ launch ============================

extern "C" void kernel_launch(void* const* d_in, const int* in_sizes, int n_in,
                              void* d_out, int out_size) {
    const int*   users   = (const int*)d_in[0];
    const float* emb     = (const float*)d_in[1];
    const float* w       = (const float*)d_in[2];
    const int*   adj_row = (const int*)d_in[3];
    const int*   adj_col = (const int*)d_in[4];
    float*       out     = (float*)d_out;

    cudaFuncSetAttribute(k_gemm, cudaFuncAttributeMaxDynamicSharedMemorySize, GEMM_SMEM);

    // CSR build
    k_zero_cnt<<<(NROWS + 255) / 256, 256>>>();
    k_hist<<<(NNZ + 255) / 256, 256>>>(adj_row);
    k_scanA<<<SCAN_NBLK, SCAN_BLOCK>>>();
    k_scanB<<<1, 256>>>();
    k_scanC<<<SCAN_NBLK, SCAN_BLOCK>>>();
    k_scatter<<<(NNZ + 255) / 256, 256>>>(adj_row, adj_col);

    // SpMM chain: half-warp per row -> 16 rows per 256-thread block
    k_spmm_feat<<<(NROWS * 16 + 255) / 256, 256>>>(emb, w);     // -> z0
    k_spmm_adj<<<(NROWS * 16 + 255) / 256, 256>>>(1);           // z0 -> z1
    k_spmm_adj<<<(NROWS * 16 + 255) / 256, 256>>>(2);           // z1 -> z2
    k_spmm_adj3_items<<<(N_ITEMS * 16 + 255) / 256, 256>>>();   // z2 -> item bf16 tiles
    k_pad_items<<<1, 512>>>();
    k_users<<<(BATCH * 16 + 255) / 256, 256>>>(users);          // -> user bf16 tiles

    dim3 gg(4, (N_ITEMS + 127) / 128);   // (mt, jblk) = (4, 1172)
    k_gemm<<<gg, 256, GEMM_SMEM>>>(out);
}

// round 17
// speedup vs baseline: 1.8112x; 1.0004x over previous
#include <cuda_runtime.h>
#include <cuda_bf16.h>
#include <cstdint>

#define N_USERS 100000
#define N_ITEMS 150000
#define NROWS   250000
#define NNZ     4000000
#define EMB     64
#define BATCH   512
#define N_ITEMS_PAD 150016   // 1172 * 128

#define SCAN_BLOCK 1024
#define SCAN_NBLK  ((NROWS + SCAN_BLOCK - 1) / SCAN_BLOCK)   // 245

// -------- device scratch (no allocations allowed) --------
__device__ int   g_cnt[NROWS];
__device__ int   g_rowptr[NROWS + 1];
__device__ int   g_rowpos[NROWS];
__device__ int   g_col[NNZ];
__device__ int   g_bsum[SCAN_NBLK];
__device__ float g_z[3][(size_t)NROWS * EMB];       // z0, z1, z2 (64 MB each)
// packed bf16 tiles (2 bf16 per u32, 32 u32 per 64-dim row)
__device__ uint32_t g_ibufH[(size_t)N_ITEMS_PAD * 32];
__device__ uint32_t g_ibufL[(size_t)N_ITEMS_PAD * 32];
__device__ uint32_t g_ubufH[BATCH * 32];
__device__ uint32_t g_ubufL[BATCH * 32];

// ============================ CSR build ============================

__global__ void k_zero_cnt() {
    int i = blockIdx.x * blockDim.x + threadIdx.x;
    if (i < NROWS) g_cnt[i] = 0;
}

__global__ void k_hist(const int* __restrict__ row) {
    int i = blockIdx.x * blockDim.x + threadIdx.x;
    if (i < NNZ) atomicAdd(&g_cnt[row[i]], 1);
}

__global__ void k_scanA() {
    __shared__ int sdata[SCAN_BLOCK];
    int i = blockIdx.x * SCAN_BLOCK + threadIdx.x;
    sdata[threadIdx.x] = (i < NROWS) ? g_cnt[i] : 0;
    __syncthreads();
    for (int s = SCAN_BLOCK / 2; s > 0; s >>= 1) {
        if (threadIdx.x < s) sdata[threadIdx.x] += sdata[threadIdx.x + s];
        __syncthreads();
    }
    if (threadIdx.x == 0) g_bsum[blockIdx.x] = sdata[0];
}

__global__ void k_scanB() {
    __shared__ int s[256];
    int t = threadIdx.x;
    int v = (t < SCAN_NBLK) ? g_bsum[t] : 0;
    s[t] = v;
    __syncthreads();
    #pragma unroll
    for (int off = 1; off < 256; off <<= 1) {
        int x = (t >= off) ? s[t - off] : 0;
        __syncthreads();
        s[t] += x;
        __syncthreads();
    }
    if (t < SCAN_NBLK) g_bsum[t] = s[t] - v;   // exclusive
}

__global__ void k_scanC() {
    __shared__ int s[SCAN_BLOCK];
    int i = blockIdx.x * SCAN_BLOCK + threadIdx.x;
    int v = (i < NROWS) ? g_cnt[i] : 0;
    s[threadIdx.x] = v;
    __syncthreads();
    #pragma unroll
    for (int off = 1; off < SCAN_BLOCK; off <<= 1) {
        int t = (threadIdx.x >= off) ? s[threadIdx.x - off] : 0;
        __syncthreads();
        s[threadIdx.x] += t;
        __syncthreads();
    }
    int excl = s[threadIdx.x] - v + g_bsum[blockIdx.x];
    if (i < NROWS) { g_rowptr[i] = excl; g_rowpos[i] = excl; }
    if (i == NROWS) g_rowptr[NROWS] = excl;
}

__global__ void k_scatter(const int* __restrict__ row, const int* __restrict__ col) {
    int i = blockIdx.x * blockDim.x + threadIdx.x;
    if (i < NNZ) {
        int r = row[i];
        int p = atomicAdd(&g_rowpos[r], 1);
        g_col[p] = col[i];
    }
}

// ============================ SpMM kernels ============================
// half-warp per row: 16 lanes x float4 (16 B) cover the 64-dim row.
// 2 rows per warp, 4-edge unroll -> 8 LDG.128 gathers in flight per warp.

__global__ void k_spmm_feat(const float* __restrict__ emb, const float* __restrict__ w) {
    int idx  = blockIdx.x * blockDim.x + threadIdx.x;
    int r    = idx >> 4;
    int lane = idx & 15;
    if (r >= NROWS) return;
    int start = g_rowptr[r], end = g_rowptr[r + 1];
    int cnt = end - start;

    const float4* emb4 = (const float4*)emb;
    int sel = (r < N_USERS) ? NROWS : (NROWS + 1);
    float4 s = __ldg(&emb4[(size_t)sel * 16 + lane]);

    int e = start;
    for (; e + 4 <= end; e += 4) {
        int c0 = __ldg(&g_col[e]);
        int c1 = __ldg(&g_col[e + 1]);
        int c2 = __ldg(&g_col[e + 2]);
        int c3 = __ldg(&g_col[e + 3]);
        float4 v0 = __ldg(&emb4[(size_t)c0 * 16 + lane]);
        float4 v1 = __ldg(&emb4[(size_t)c1 * 16 + lane]);
        float4 v2 = __ldg(&emb4[(size_t)c2 * 16 + lane]);
        float4 v3 = __ldg(&emb4[(size_t)c3 * 16 + lane]);
        s.x += (v0.x + v1.x) + (v2.x + v3.x);
        s.y += (v0.y + v1.y) + (v2.y + v3.y);
        s.z += (v0.z + v1.z) + (v2.z + v3.z);
        s.w += (v0.w + v1.w) + (v2.w + v3.w);
    }
    for (; e < end; e++) {
        int c = __ldg(&g_col[e]);
        float4 v = __ldg(&emb4[(size_t)c * 16 + lane]);
        s.x += v.x; s.y += v.y; s.z += v.z; s.w += v.w;
    }

    float scale = rsqrtf((float)(cnt + 1)) * rsqrtf((float)(cnt > 0 ? cnt : 1));
    float4 wv = __ldg(((const float4*)w) + lane);
    float4 z;
    z.x = s.x * wv.x * scale;
    z.y = s.y * wv.y * scale;
    z.z = s.z * wv.z * scale;
    z.w = s.w * wv.w * scale;
    ((float4*)g_z[0])[(size_t)r * 16 + lane] = z;
}

__global__ void k_spmm_adj(int layer) {   // full passes: layer = 1, 2
    int idx  = blockIdx.x * blockDim.x + threadIdx.x;
    int r    = idx >> 4;
    int lane = idx & 15;
    if (r >= NROWS) return;
    const float4* zin  = (const float4*)g_z[layer - 1];
    float4*       zout = (float4*)g_z[layer];

    int start = g_rowptr[r], end = g_rowptr[r + 1];
    int cnt = end - start;

    float4 s = make_float4(0.f, 0.f, 0.f, 0.f);
    int e = start;
    for (; e + 4 <= end; e += 4) {
        int c0 = __ldg(&g_col[e]);
        int c1 = __ldg(&g_col[e + 1]);
        int c2 = __ldg(&g_col[e + 2]);
        int c3 = __ldg(&g_col[e + 3]);
        float4 v0 = __ldg(&zin[(size_t)c0 * 16 + lane]);
        float4 v1 = __ldg(&zin[(size_t)c1 * 16 + lane]);
        float4 v2 = __ldg(&zin[(size_t)c2 * 16 + lane]);
        float4 v3 = __ldg(&zin[(size_t)c3 * 16 + lane]);
        s.x += (v0.x + v1.x) + (v2.x + v3.x);
        s.y += (v0.y + v1.y) + (v2.y + v3.y);
        s.z += (v0.z + v1.z) + (v2.z + v3.z);
        s.w += (v0.w + v1.w) + (v2.w + v3.w);
    }
    for (; e < end; e++) {
        int c = __ldg(&g_col[e]);
        float4 v = __ldg(&zin[(size_t)c * 16 + lane]);
        s.x += v.x; s.y += v.y; s.z += v.z; s.w += v.w;
    }

    float s2 = 1.f / (float)(cnt > 0 ? cnt : 1);   // d_inv^2
    float4 z; z.x = s.x * s2; z.y = s.y * s2; z.z = s.z * s2; z.w = s.w * s2;
    zout[(size_t)r * 16 + lane] = z;
}

// ============================ bf16 hi/lo helpers ============================

__device__ __forceinline__ void split2(float x, float y, uint32_t& hi, uint32_t& lo) {
    __nv_bfloat16 hx = __float2bfloat16(x), hy = __float2bfloat16(y);
    hi = (uint32_t)__bfloat16_as_ushort(hx) | ((uint32_t)__bfloat16_as_ushort(hy) << 16);
    __nv_bfloat16 lx = __float2bfloat16(x - __bfloat162float(hx));
    __nv_bfloat16 ly = __float2bfloat16(y - __bfloat162float(hy));
    lo = (uint32_t)__bfloat16_as_ushort(lx) | ((uint32_t)__bfloat16_as_ushort(ly) << 16);
}

// pass 3, item rows only, fused with item-tile prep:
// z3 = dinv2 * sum(z2[cols]); v = (z0+z1+z2+z3)*0.25*sqrt(deg) -> bf16 hi/lo
__global__ void k_spmm_adj3_items() {
    int idx  = blockIdx.x * blockDim.x + threadIdx.x;
    int hw   = idx >> 4;          // item index
    int lane = idx & 15;
    if (hw >= N_ITEMS) return;
    int r = N_USERS + hw;
    int start = g_rowptr[r], end = g_rowptr[r + 1];
    int cnt = end - start;

    const float4* zin = (const float4*)g_z[2];
    float4 s = make_float4(0.f, 0.f, 0.f, 0.f);
    int e = start;
    for (; e + 4 <= end; e += 4) {
        int c0 = __ldg(&g_col[e]);
        int c1 = __ldg(&g_col[e + 1]);
        int c2 = __ldg(&g_col[e + 2]);
        int c3 = __ldg(&g_col[e + 3]);
        float4 v0 = __ldg(&zin[(size_t)c0 * 16 + lane]);
        float4 v1 = __ldg(&zin[(size_t)c1 * 16 + lane]);
        float4 v2 = __ldg(&zin[(size_t)c2 * 16 + lane]);
        float4 v3 = __ldg(&zin[(size_t)c3 * 16 + lane]);
        s.x += (v0.x + v1.x) + (v2.x + v3.x);
        s.y += (v0.y + v1.y) + (v2.y + v3.y);
        s.z += (v0.z + v1.z) + (v2.z + v3.z);
        s.w += (v0.w + v1.w) + (v2.w + v3.w);
    }
    for (; e < end; e++) {
        int c = __ldg(&g_col[e]);
        float4 v = __ldg(&zin[(size_t)c * 16 + lane]);
        s.x += v.x; s.y += v.y; s.z += v.z; s.w += v.w;
    }

    float s2 = 1.f / (float)(cnt > 0 ? cnt : 1);
    size_t o = (size_t)r * 16 + lane;
    float4 a = __ldg((const float4*)g_z[0] + o);
    float4 b = __ldg((const float4*)g_z[1] + o);
    float4 c = __ldg((const float4*)g_z[2] + o);
    float sc = 0.25f * sqrtf((float)(cnt > 0 ? cnt : 1));
    float4 v;
    v.x = (a.x + b.x + c.x + s.x * s2) * sc;
    v.y = (a.y + b.y + c.y + s.y * s2) * sc;
    v.z = (a.z + b.z + c.z + s.z * s2) * sc;
    v.w = (a.w + b.w + c.w + s.w * s2) * sc;

    uint32_t h0, l0, h1, l1;
    split2(v.x, v.y, h0, l0);
    split2(v.z, v.w, h1, l1);
    ((uint2*)g_ibufH)[(size_t)hw * 16 + lane] = make_uint2(h0, h1);
    ((uint2*)g_ibufL)[(size_t)hw * 16 + lane] = make_uint2(l0, l1);
}

__global__ void k_pad_items() {
    int i = blockIdx.x * blockDim.x + threadIdx.x;
    if (i < (N_ITEMS_PAD - N_ITEMS) * 32) {
        g_ibufH[(size_t)N_ITEMS * 32 + i] = 0;
        g_ibufL[(size_t)N_ITEMS * 32 + i] = 0;
    }
}

// user prep: z3[u] computed on the fly from z2 (pass 3 skipped user rows)
__global__ void k_users(const int* __restrict__ users) {
    int idx  = blockIdx.x * blockDim.x + threadIdx.x;
    int hw   = idx >> 4;          // batch index
    int lane = idx & 15;
    if (hw >= BATCH) return;
    int u = __ldg(&users[hw]);
    int start = g_rowptr[u], end = g_rowptr[u + 1];
    int cnt = end - start;

    const float4* zin = (const float4*)g_z[2];
    float4 s = make_float4(0.f, 0.f, 0.f, 0.f);
    for (int e = start; e < end; e++) {
        int c = __ldg(&g_col[e]);
        float4 v = __ldg(&zin[(size_t)c * 16 + lane]);
        s.x += v.x; s.y += v.y; s.z += v.z; s.w += v.w;
    }
    float s2 = 1.f / (float)(cnt > 0 ? cnt : 1);
    size_t o = (size_t)u * 16 + lane;
    float4 a = __ldg((const float4*)g_z[0] + o);
    float4 b = __ldg((const float4*)g_z[1] + o);
    float4 c = __ldg((const float4*)g_z[2] + o);
    float sc = 0.25f * sqrtf((float)(cnt > 0 ? cnt : 1));
    float4 v;
    v.x = (a.x + b.x + c.x + s.x * s2) * sc;
    v.y = (a.y + b.y + c.y + s.y * s2) * sc;
    v.z = (a.z + b.z + c.z + s.z * s2) * sc;
    v.w = (a.w + b.w + c.w + s.w * s2) * sc;

    uint32_t h0, l0, h1, l1;
    split2(v.x, v.y, h0, l0);
    split2(v.z, v.w, h1, l1);
    ((uint2*)g_ubufH)[(size_t)hw * 16 + lane] = make_uint2(h0, h1);
    ((uint2*)g_ubufL)[(size_t)hw * 16 + lane] = make_uint2(l0, l1);
}

// ============================ HMMA bf16 GEMM ============================
// out[512, 150000] = U @ I^T, hi/lo split: Ah*Bh + Ah*Bl + Al*Bh.
// CTA = 128 users x 128 items; 8 warps (2x4), warp tile 64x32.

#define SWZ(o) ((o) ^ (((o) >> 3) & 0x70))

__device__ __forceinline__ uint32_t smem_u32(const void* p) {
    uint32_t a;
    asm("{ .reg .u64 t; cvta.to.shared.u64 t, %1; cvt.u32.u64 %0, t; }"
        : "=r"(a) : "l"(p));
    return a;
}

#define LDSM4(r0, r1, r2, r3, addr) \
    asm volatile("ldmatrix.sync.aligned.m8n8.x4.shared.b16 {%0,%1,%2,%3}, [%4];" \
        : "=r"(r0), "=r"(r1), "=r"(r2), "=r"(r3) : "r"(addr))

#define MMA16816(c, a, b0, b1) \
    asm volatile("mma.sync.aligned.m16n8k16.row.col.f32.bf16.bf16.f32 " \
        "{%0,%1,%2,%3}, {%4,%5,%6,%7}, {%8,%9}, {%0,%1,%2,%3};" \
        : "+f"((c)[0]), "+f"((c)[1]), "+f"((c)[2]), "+f"((c)[3]) \
        : "r"((a)[0]), "r"((a)[1]), "r"((a)[2]), "r"((a)[3]), "r"(b0), "r"(b1))

#define GEMM_SMEM 65536   // 4 tiles x 16KB (Ah, Al, Bh, Bl)

__global__ __launch_bounds__(256) void k_gemm(float* __restrict__ out) {
    extern __shared__ char sm[];
    char* sAh = sm;
    char* sAl = sm + 16384;
    char* sBh = sm + 32768;
    char* sBl = sm + 49152;

    int t    = threadIdx.x;
    int wid  = t >> 5, lane = t & 31;
    int mt   = blockIdx.x;     // user tile 0..3   (fast -> item tile L2 reuse)
    int jblk = blockIdx.y;     // item tile 0..1171

    {
        const uint4* aH = (const uint4*)(g_ubufH + (size_t)mt * 128 * 32);
        const uint4* aL = (const uint4*)(g_ubufL + (size_t)mt * 128 * 32);
        const uint4* bH = (const uint4*)(g_ibufH + (size_t)jblk * 128 * 32);
        const uint4* bL = (const uint4*)(g_ibufL + (size_t)jblk * 128 * 32);
        #pragma unroll
        for (int q = 0; q < 4; q++) {
            int idx = q * 256 + t;                 // 1024 uint4 per tile
            uint32_t off = SWZ((uint32_t)(idx * 16));
            *(uint4*)(sAh + off) = aH[idx];
            *(uint4*)(sAl + off) = aL[idx];
            *(uint4*)(sBh + off) = bH[idx];
            *(uint4*)(sBl + off) = bL[idx];
        }
    }
    __syncthreads();

    int wm = wid >> 2;            // 0..1 -> m_base 0/64
    int wn = wid & 3;             // 0..3 -> n_base 0/32/64/96
    int m_base = wm * 64;
    int n_base = wn * 32;

    int a_row = m_base + (lane & 15);
    int a_kc  = (lane >> 4) * 16;
    int b_row = n_base + (lane & 7) + ((lane >> 4) << 3);
    int b_kc  = ((lane >> 3) & 1) * 16;

    float acc[4][4][4];
    #pragma unroll
    for (int i = 0; i < 4; i++)
        #pragma unroll
        for (int j = 0; j < 4; j++)
            #pragma unroll
            for (int q = 0; q < 4; q++) acc[i][j][q] = 0.f;

    const char* Ap[3] = { sAh, sAh, sAl };
    const char* Bp[3] = { sBh, sBl, sBh };

    #pragma unroll
    for (int p = 0; p < 3; p++) {
        #pragma unroll
        for (int ks = 0; ks < 4; ks++) {        // K = 64, 16 per step = 32 B
            uint32_t a[4][4];
            #pragma unroll
            for (int mi = 0; mi < 4; mi++) {
                uint32_t off = SWZ((uint32_t)((a_row + mi * 16) * 128 + ks * 32 + a_kc));
                uint32_t ad = smem_u32(Ap[p] + off);
                LDSM4(a[mi][0], a[mi][1], a[mi][2], a[mi][3], ad);
            }
            uint32_t bb[2][4];
            #pragma unroll
            for (int nh = 0; nh < 2; nh++) {
                uint32_t off = SWZ((uint32_t)((b_row + nh * 16) * 128 + ks * 32 + b_kc));
                uint32_t ad = smem_u32(Bp[p] + off);
                LDSM4(bb[nh][0], bb[nh][1], bb[nh][2], bb[nh][3], ad);
            }
            #pragma unroll
            for (int mi = 0; mi < 4; mi++)
                #pragma unroll
                for (int nj = 0; nj < 4; nj++)
                    MMA16816(acc[mi][nj], a[mi],
                             bb[nj >> 1][(nj & 1) * 2],
                             bb[nj >> 1][(nj & 1) * 2 + 1]);
        }
    }

    int gj0 = jblk * 128 + n_base;
    #pragma unroll
    for (int mi = 0; mi < 4; mi++) {
        int r0 = mt * 128 + m_base + mi * 16 + (lane >> 2);
        float* row0 = out + (size_t)r0 * N_ITEMS;
        float* row1 = row0 + (size_t)8 * N_ITEMS;
        #pragma unroll
        for (int nj = 0; nj < 4; nj++) {
            int c = gj0 + nj * 8 + (lane & 3) * 2;
            if (c < N_ITEMS) {
                *(float2*)(row0 + c) = make_float2(acc[mi][nj][0], acc[mi][nj][1]);
                *(float2*)(row1 + c) = make_float2(acc[mi][nj][2], acc[mi][nj][3]);
            }
        }
    }
}

// ============================ launch ============================

extern "C" void kernel_launch(void* const* d_in, const int* in_sizes, int n_in,
                              void* d_out, int out_size) {
    const int*   users   = (const int*)d_in[0];
    const float* emb     = (const float*)d_in[1];
    const float* w       = (const float*)d_in[2];
    const int*   adj_row = (const int*)d_in[3];
    const int*   adj_col = (const int*)d_in[4];
    float*       out     = (float*)d_out;

    cudaFuncSetAttribute(k_gemm, cudaFuncAttributeMaxDynamicSharedMemorySize, GEMM_SMEM);

    // CSR build
    k_zero_cnt<<<(NROWS + 255) / 256, 256>>>();
    k_hist<<<(NNZ + 255) / 256, 256>>>(adj_row);
    k_scanA<<<SCAN_NBLK, SCAN_BLOCK>>>();
    k_scanB<<<1, 256>>>();
    k_scanC<<<SCAN_NBLK, SCAN_BLOCK>>>();
    k_scatter<<<(NNZ + 255) / 256, 256>>>(adj_row, adj_col);

    // SpMM chain: half-warp per row -> 16 rows per 256-thread block
    k_spmm_feat<<<(NROWS * 16 + 255) / 256, 256>>>(emb, w);     // -> z0
    k_spmm_adj<<<(NROWS * 16 + 255) / 256, 256>>>(1);           // z0 -> z1
    k_spmm_adj<<<(NROWS * 16 + 255) / 256, 256>>>(2);           // z1 -> z2
    k_spmm_adj3_items<<<(N_ITEMS * 16 + 255) / 256, 256>>>();   // z2 -> item bf16 tiles
    k_pad_items<<<1, 512>>>();
    k_users<<<(BATCH * 16 + 255) / 256, 256>>>(users);          // -> user bf16 tiles

    dim3 gg(4, (N_ITEMS + 127) / 128);   // (mt, jblk) = (4, 1172)
    k_gemm<<<gg, 256, GEMM_SMEM>>>(out);
}